// round 12
// baseline (speedup 1.0000x reference)
#include <cuda_runtime.h>
#include <cuda_fp16.h>
#include <mma.h>
#include <cstdint>

using namespace nvcuda;

#define N_NODES 50000
#define N_EDGES 800000
#define IN_CH   256
#define HC      128
#define EPS_F   1.000001f

// ================= scratch (static device arrays; no allocation) =================
__device__ __half g_X16[(size_t)N_NODES * IN_CH];   // X in fp16
__device__ __half g_Bt[3][HC][IN_CH];               // [mat][n][k]  (B = W^T, fp16; skip pre-scaled by EPS)
__device__ __half g_xh[2][(size_t)N_NODES * HC];    // fp16 messages: x@Wl, x@Wu
__device__ float  g_xs[(size_t)N_NODES * HC];       // fp32 skip: (x@Ws)*EPS
__device__ float2 g_alpha[4][N_NODES];              // [l_src, l_dst, u_src, u_dst][n] = (h0,h1)
__device__ int    g_rp[2][N_NODES + 1];             // CSR row ptr (tgt sorted)

__device__ __forceinline__ uint32_t smem_u32(const void* p) {
    uint32_t a;
    asm("{ .reg .u64 t; cvta.to.shared.u64 t, %1; cvt.u32.u64 %0, t; }" : "=r"(a) : "l"(p));
    return a;
}
__device__ __forceinline__ void cp16(uint32_t dst, const void* src, int nbytes) {
    asm volatile("cp.async.cg.shared.global [%0], [%1], 16, %2;" :: "r"(dst), "l"(src), "r"(nbytes));
}
#define CP_COMMIT() asm volatile("cp.async.commit_group;" ::: "memory")
#define CP_WAIT0()  asm volatile("cp.async.wait_group 0;" ::: "memory")

// ================= 0) X -> fp16 =================
__global__ void x2h_kernel(const float* __restrict__ X) {
    int f = blockIdx.x * blockDim.x + threadIdx.x;       // one per 8 elements
    if (f >= N_NODES * IN_CH / 8) return;
    size_t base = (size_t)f * 8;
    float4 v0 = *(const float4*)(X + base);
    float4 v1 = *(const float4*)(X + base + 4);
    __half2 h0 = __floats2half2_rn(v0.x, v0.y);
    __half2 h1 = __floats2half2_rn(v0.z, v0.w);
    __half2 h2 = __floats2half2_rn(v1.x, v1.y);
    __half2 h3 = __floats2half2_rn(v1.z, v1.w);
    uint4 o = make_uint4(*(uint32_t*)&h0, *(uint32_t*)&h1, *(uint32_t*)&h2, *(uint32_t*)&h3);
    *(uint4*)(g_X16 + base) = o;
}

// ================= 1) B = W^T in fp16 (skip matrix pre-scaled by EPS) =================
__global__ void prep_bt(const float* __restrict__ Wl, const float* __restrict__ Wu,
                        const float* __restrict__ Ws) {
    int i = blockIdx.x * blockDim.x + threadIdx.x;
    if (i >= 3 * HC * IN_CH) return;
    int mat = i / (HC * IN_CH);
    int r   = i % (HC * IN_CH);
    int n = r / IN_CH, k = r % IN_CH;
    const float* W = (mat == 0) ? Wl : (mat == 1 ? Wu : Ws);
    float w = W[k * HC + n];
    if (mat == 2) w *= EPS_F;
    g_Bt[mat][n][k] = __float2half(w);
}

// ================= 2) row pointers via binary search =================
__global__ void rowptr_kernel(const int* __restrict__ ltgt, const int* __restrict__ utgt) {
    int t = blockIdx.x * blockDim.x + threadIdx.x;
    if (t > N_NODES) return;
    #pragma unroll
    for (int s = 0; s < 2; s++) {
        const int* tg = (s == 0) ? ltgt : utgt;
        int lo = 0, hi = N_EDGES;
        while (lo < hi) {
            int mid = (lo + hi) >> 1;
            if (tg[mid] < t) lo = mid + 1; else hi = mid;
        }
        g_rp[s][t] = lo;
    }
}

// ================= 3) fp16 wmma GEMM: 512 threads / 16 warps, BM=256, cp.async =================
// grid = (3 matrices, 196 M-tiles); warp grid 8x2, warp tile 32x64
#define NT      512
#define BM      256
#define KC      64
#define NCHUNK  (IN_CH / KC)     // 4
#define LDA     72               // 64 + 8 pad (fp16); odd 8-granules -> LDSM conflict-free
#define LDB     264
#define ABUF    (BM * LDA)       // halves per A buffer (36864 B)
#define SM_AVEC 0                // 256 floats
#define SM_A    1024
#define SM_B    (SM_A + 2 * ABUF * 2)           // 1024 + 73728 = 74752
#define SM_TOTAL (SM_B + 128 * LDB * 2)         // 74752 + 67584 = 142336 B
#define LDC     132

__global__ __launch_bounds__(NT) void gemm_wmma(const float* __restrict__ asl, const float* __restrict__ adl,
                                                const float* __restrict__ asu, const float* __restrict__ adu) {
    extern __shared__ __align__(16) char smem[];
    float* avec = (float*)(smem + SM_AVEC);
    __half* Bs = (__half*)(smem + SM_B);
    const uint32_t smA = smem_u32(smem) + SM_A;

    const int tid = threadIdx.x;
    const int wid = tid >> 5;
    const int bx  = blockIdx.x;                 // matrix 0=lower,1=upper,2=skip
    const int m0  = blockIdx.y * BM;
    const int wm  = wid & 7;                    // 8 row groups of 32
    const int wn  = wid >> 3;                   // 2 col groups of 64

    if (bx < 2 && tid < 256) {
        const float* av = (tid < 128) ? (bx ? asu : asl) : (bx ? adu : adl);
        avec[tid] = av[tid & 127];
    }

    // ---- B resident: 128 rows x 256 cols fp16 ----
    #pragma unroll
    for (int t = 0; t < 8; t++) {
        int f = tid + t * NT;
        int n = f >> 5, seg = f & 31;
        uint4 v = *(const uint4*)&g_Bt[bx][n][seg * 8];
        *(uint4*)(Bs + n * LDB + seg * 8) = v;
    }

    wmma::fragment<wmma::accumulator, 16, 16, 16, float> acc[2][4];
    #pragma unroll
    for (int i = 0; i < 2; i++)
        #pragma unroll
        for (int j = 0; j < 4; j++)
            wmma::fill_fragment(acc[i][j], 0.0f);

    // ---- cp.async A chunk issue: 256 rows x 8 x 16B segs ----
    auto issue_chunk = [&](int c) {
        uint32_t Ab = smA + (c & 1) * (ABUF * 2);
        #pragma unroll
        for (int t = 0; t < 4; t++) {
            int f = tid + t * NT;                // 0..2047
            int row = f >> 3, seg = f & 7;
            int m = m0 + row;
            int mc = (m < N_NODES) ? m : (N_NODES - 1);
            const __half* src = g_X16 + (size_t)mc * IN_CH + c * KC + seg * 8;
            cp16(Ab + (row * LDA + seg * 8) * 2, src, (m < N_NODES) ? 16 : 0);
        }
        CP_COMMIT();
    };

    issue_chunk(0);

    for (int c = 0; c < NCHUNK; c++) {
        CP_WAIT0();
        __syncthreads();     // copies visible; all warps done mma on buffer (c-1)&1
        if (c + 1 < NCHUNK) issue_chunk(c + 1);   // overlaps with mma on chunk c

        const __half* Ab = (const __half*)(smem + SM_A) + (c & 1) * ABUF;
        #pragma unroll
        for (int ks = 0; ks < KC / 16; ks++) {
            wmma::fragment<wmma::matrix_a, 16, 16, 16, __half, wmma::row_major> fa[2];
            wmma::fragment<wmma::matrix_b, 16, 16, 16, __half, wmma::col_major> fb[4];
            #pragma unroll
            for (int i = 0; i < 2; i++)
                wmma::load_matrix_sync(fa[i], Ab + (wm * 32 + i * 16) * LDA + ks * 16, LDA);
            #pragma unroll
            for (int j = 0; j < 4; j++)
                wmma::load_matrix_sync(fb[j], Bs + (wn * 64 + j * 16) * LDB + c * KC + ks * 16, LDB);
            #pragma unroll
            for (int i = 0; i < 2; i++)
                #pragma unroll
                for (int j = 0; j < 4; j++)
                    wmma::mma_sync(acc[i][j], fa[i], fb[j], acc[i][j]);
        }
    }
    __syncthreads();

    // --- epilogue: stage C (256 x 132 fp32 = 135168 B, fits in A+B region) ---
    float* Cs = (float*)(smem + SM_A);
    #pragma unroll
    for (int i = 0; i < 2; i++)
        #pragma unroll
        for (int j = 0; j < 4; j++)
            wmma::store_matrix_sync(Cs + (wm * 32 + i * 16) * LDC + wn * 64 + j * 16,
                                    acc[i][j], LDC, wmma::mem_row_major);
    __syncthreads();

    {
        const int r = tid >> 1;                 // row in tile 0..255
        const int h = tid & 1;                  // half (= head) 0/1
        const int m = m0 + r;
        float ss = 0.f, dd = 0.f;
        if (m < N_NODES) {
            const float* crow = Cs + r * LDC + h * 64;
            if (bx == 2) {
                float* dst = g_xs + (size_t)m * HC + h * 64;
                #pragma unroll
                for (int q = 0; q < 16; q++)
                    *(float4*)(dst + q * 4) = *(const float4*)(crow + q * 4);
            } else {
                __half* dst = g_xh[bx] + (size_t)m * HC + h * 64;
                const float* avs = avec + h * 64;
                const float* avd = avec + 128 + h * 64;
                #pragma unroll
                for (int q = 0; q < 16; q++) {
                    float4 v = *(const float4*)(crow + q * 4);
                    ss = fmaf(v.x, avs[q*4+0], ss); ss = fmaf(v.y, avs[q*4+1], ss);
                    ss = fmaf(v.z, avs[q*4+2], ss); ss = fmaf(v.w, avs[q*4+3], ss);
                    dd = fmaf(v.x, avd[q*4+0], dd); dd = fmaf(v.y, avd[q*4+1], dd);
                    dd = fmaf(v.z, avd[q*4+2], dd); dd = fmaf(v.w, avd[q*4+3], dd);
                    __half2 p0 = __floats2half2_rn(v.x, v.y);
                    __half2 p1 = __floats2half2_rn(v.z, v.w);
                    *(uint2*)(dst + q * 4) = make_uint2(*(uint32_t*)&p0, *(uint32_t*)&p1);
                }
            }
        }
        if (bx < 2) {
            float ss_o = __shfl_xor_sync(0xFFFFFFFF, ss, 1);
            float dd_o = __shfl_xor_sync(0xFFFFFFFF, dd, 1);
            if (h == 0 && m < N_NODES) {
                float s0 = (ss   > 0.f) ? ss   : 0.01f * ss;
                float s1 = (ss_o > 0.f) ? ss_o : 0.01f * ss_o;
                float d0 = (dd   > 0.f) ? dd   : 0.01f * dd;
                float d1 = (dd_o > 0.f) ? dd_o : 0.01f * dd_o;
                g_alpha[bx * 2 + 0][m] = make_float2(s0, s1);
                g_alpha[bx * 2 + 1][m] = make_float2(d0, d1);
            }
        }
    }
}

// ================= 4) fused aggregation: warp per target node; inline softmax =================
// Edges processed in warp-batches of 32: each lane computes one edge's sigmoid weight
// from the alpha gathers, then the gather loop consumes (w0, sn) via shfl broadcast.
__global__ __launch_bounds__(256) void out_kernel(const int* __restrict__ lsrc,
                                                  const int* __restrict__ usrc,
                                                  float* __restrict__ out) {
    int warp = (blockIdx.x * blockDim.x + threadIdx.x) >> 5;
    int lane = threadIdx.x & 31;
    if (warp >= N_NODES) return;
    const int t = warp;
    const int head = lane >> 4;

    float4 acc = *(const float4*)(g_xs + (size_t)t * HC + lane * 4);   // skip (already *EPS)

    #pragma unroll
    for (int s = 0; s < 2; s++) {
        const int*    src = (s == 0) ? lsrc : usrc;
        const __half* xh  = g_xh[s];
        const float2* asp = g_alpha[s * 2];
        const float2  at  = g_alpha[s * 2 + 1][t];
        const int beg = g_rp[s][t], end = g_rp[s][t + 1];

        for (int e0 = beg; e0 < end; e0 += 32) {
            int n = end - e0; if (n > 32) n = 32;
            int   sn_l = 0;
            float w_l  = 0.f;
            if (lane < n) {
                sn_l = src[e0 + lane];
                float2 as = asp[sn_l];
                float dlt = (as.y + at.y) - (as.x + at.x);     // s1 - s0 (edge vals cancel)
                w_l = 1.f / (1.f + __expf(dlt));
            }
            int j = 0;
            for (; j + 1 < n; j += 2) {
                int   sn0 = __shfl_sync(0xFFFFFFFF, sn_l, j);
                int   sn1 = __shfl_sync(0xFFFFFFFF, sn_l, j + 1);
                float w00 = __shfl_sync(0xFFFFFFFF, w_l, j);
                float w01 = __shfl_sync(0xFFFFFFFF, w_l, j + 1);
                uint2 u0 = *(const uint2*)(xh + (size_t)sn0 * HC + lane * 4);
                uint2 u1 = *(const uint2*)(xh + (size_t)sn1 * HC + lane * 4);
                float wa = head ? (1.f - w00) : w00;
                float wb = head ? (1.f - w01) : w01;
                float2 a0 = __half22float2(*(__half2*)&u0.x);
                float2 a1 = __half22float2(*(__half2*)&u0.y);
                float2 b0 = __half22float2(*(__half2*)&u1.x);
                float2 b1 = __half22float2(*(__half2*)&u1.y);
                acc.x = fmaf(a0.x, wa, acc.x); acc.y = fmaf(a0.y, wa, acc.y);
                acc.z = fmaf(a1.x, wa, acc.z); acc.w = fmaf(a1.y, wa, acc.w);
                acc.x = fmaf(b0.x, wb, acc.x); acc.y = fmaf(b0.y, wb, acc.y);
                acc.z = fmaf(b1.x, wb, acc.z); acc.w = fmaf(b1.y, wb, acc.w);
            }
            if (j < n) {
                int   sn = __shfl_sync(0xFFFFFFFF, sn_l, j);
                float w0 = __shfl_sync(0xFFFFFFFF, w_l, j);
                float w  = head ? (1.f - w0) : w0;
                uint2 u = *(const uint2*)(xh + (size_t)sn * HC + lane * 4);
                float2 a0 = __half22float2(*(__half2*)&u.x);
                float2 a1 = __half22float2(*(__half2*)&u.y);
                acc.x = fmaf(a0.x, w, acc.x); acc.y = fmaf(a0.y, w, acc.y);
                acc.z = fmaf(a1.x, w, acc.z); acc.w = fmaf(a1.y, w, acc.w);
            }
        }
    }
    acc.x = fmaxf(acc.x, 0.f);
    acc.y = fmaxf(acc.y, 0.f);
    acc.z = fmaxf(acc.z, 0.f);
    acc.w = fmaxf(acc.w, 0.f);
    *(float4*)(out + (size_t)t * HC + lane * 4) = acc;
}

// ================= launcher =================
extern "C" void kernel_launch(void* const* d_in, const int* in_sizes, int n_in,
                              void* d_out, int out_size) {
    const float* x    = (const float*)d_in[0];
    const int*   ltgt = (const int*)  d_in[1];
    const int*   lsrc = (const int*)  d_in[2];
    const int*   utgt = (const int*)  d_in[4];
    const int*   usrc = (const int*)  d_in[5];
    const float* Wl   = (const float*)d_in[7];
    const float* asl  = (const float*)d_in[8];
    const float* adl  = (const float*)d_in[9];
    const float* Wu   = (const float*)d_in[10];
    const float* asu  = (const float*)d_in[11];
    const float* adu  = (const float*)d_in[12];
    const float* Ws   = (const float*)d_in[13];
    float* out = (float*)d_out;

    cudaFuncSetAttribute(gemm_wmma, cudaFuncAttributeMaxDynamicSharedMemorySize, SM_TOTAL);

    x2h_kernel<<<(N_NODES * IN_CH / 8 + 255) / 256, 256>>>(x);
    prep_bt<<<(3 * HC * IN_CH + 255) / 256, 256>>>(Wl, Wu, Ws);
    rowptr_kernel<<<(N_NODES + 1 + 255) / 256, 256>>>(ltgt, utgt);

    dim3 ggrid(3, (N_NODES + BM - 1) / BM);
    gemm_wmma<<<ggrid, NT, SM_TOTAL>>>(asl, adl, asu, adu);

    out_kernel<<<(N_NODES * 32 + 255) / 256, 256>>>(lsrc, usrc, out);
}